// round 14
// baseline (speedup 1.0000x reference)
#include <cuda_runtime.h>
#include <cuda_fp16.h>
#include <cstdint>

// Problem constants
#define BB   4
#define SS   1024
#define DIN  768
#define HH   12
#define DH   64
#define WWRD (HH*DIN*DH)

// Scratch (device globals; no allocs allowed). fp16 pair-unit layouts:
// unit(row, kk, tig) = { f16x2(v[16kk+2tig], v[16kk+2tig+1]),
//                        f16x2(v[16kk+8+2tig], v[16kk+9+2tig]) }   (8 bytes)
__device__ __align__(16) uint32_t g_Xf16[BB*SS*DIN/2];        // [row][kk48][tig4]
__device__ __align__(16) uint32_t g_Wf16[3*WWRD/2];           // [(m,h)][kc24][n64][u8]
__device__ __align__(16) float    g_Qf  [BB*HH*SS*DH];        // fp32 [b,h,s,e] (pre-scaled 1/8)
__device__ __align__(16) uint32_t g_Kf16[(size_t)BB*HH*SS*DH/2]; // [s][u16][2w] per (b,h)
__device__ __align__(16) uint32_t g_Vf16[(size_t)BB*HH*DH*SS/2]; // [e][K0*4+tig][2w]

// ---------------------------------------------------------------------------
// helpers
// ---------------------------------------------------------------------------
__device__ __forceinline__ uint32_t pkh(float a, float b) {
    __half2 h = __floats2half2_rn(a, b);
    return *reinterpret_cast<uint32_t*>(&h);
}

__device__ __forceinline__ void mma_f16(float c[4],
                                        uint32_t a0, uint32_t a1, uint32_t a2, uint32_t a3,
                                        uint32_t b0, uint32_t b1) {
    asm volatile(
        "mma.sync.aligned.m16n8k16.row.col.f32.f16.f16.f32 "
        "{%0,%1,%2,%3}, {%4,%5,%6,%7}, {%8,%9}, {%0,%1,%2,%3};"
        : "+f"(c[0]), "+f"(c[1]), "+f"(c[2]), "+f"(c[3])
        : "r"(a0), "r"(a1), "r"(a2), "r"(a3), "r"(b0), "r"(b1));
}

__device__ __forceinline__ void cpa16(uint32_t smem_addr, const void* gptr) {
    asm volatile("cp.async.cg.shared.global [%0], [%1], 16;"
                 :: "r"(smem_addr), "l"(gptr));
}
__device__ __forceinline__ void cpa_commit() {
    asm volatile("cp.async.commit_group;");
}
template <int N>
__device__ __forceinline__ void cpa_wait() {
    asm volatile("cp.async.wait_group %0;" :: "n"(N));
}

// ---------------------------------------------------------------------------
// Kernel 0a: x fp32 -> fp16 pair units. One (row, kk16) per thread.
// ---------------------------------------------------------------------------
__global__ __launch_bounds__(256)
void prep_x(const float* __restrict__ x) {
    int idx = blockIdx.x*256 + threadIdx.x;      // 0..196607
    int row = idx / 48, kk = idx % 48;
    const float4* src = (const float4*)(x + (size_t)row*DIN + kk*16);
    float4 v0 = src[0], v1 = src[1], v2 = src[2], v3 = src[3];
    float f[16] = {v0.x,v0.y,v0.z,v0.w, v1.x,v1.y,v1.z,v1.w,
                   v2.x,v2.y,v2.z,v2.w, v3.x,v3.y,v3.z,v3.w};
    uint32_t w[8];
    #pragma unroll
    for (int tg = 0; tg < 4; tg++) {
        w[tg*2]   = pkh(f[2*tg],     f[2*tg + 1]);
        w[tg*2+1] = pkh(f[8 + 2*tg], f[9 + 2*tg]);
    }
    uint4* dst = (uint4*)&g_Xf16[(size_t)row*384 + kk*8];
    dst[0] = *(uint4*)&w[0];
    dst[1] = *(uint4*)&w[4];
}

// ---------------------------------------------------------------------------
// Kernel 0b: W [h][k][n] fp32 -> fp16 pair units [(m,h)][kc][n][u8].
// Wq is pre-scaled by 0.125 (exact) so attention scores need no scaling.
// grid (24 kc, 12 h, 3 m), 256 threads, smem bounce.
// ---------------------------------------------------------------------------
__global__ __launch_bounds__(256)
void prep_w(const float* __restrict__ Wq, const float* __restrict__ Wk,
            const float* __restrict__ Wv) {
    __shared__ float sm[32*65];
    const int kc = blockIdx.x, h = blockIdx.y, m = blockIdx.z;
    const int tid = threadIdx.x;
    const float scale = (m == 0) ? 0.125f : 1.0f;
    const float* src = ((m == 0) ? Wq : (m == 1) ? Wk : Wv)
                       + (size_t)h*DIN*DH + (size_t)kc*32*DH;
    #pragma unroll
    for (int it = 0; it < 8; it++) {
        int idx = tid + it*256;            // 0..2047
        int k = idx >> 6, n = idx & 63;
        sm[k*65 + n] = scale * src[k*64 + n];
    }
    __syncthreads();
    uint32_t* dst = g_Wf16 + ((size_t)((m*HH + h)*24 + kc))*1024;  // 64n x 16w
    #pragma unroll
    for (int it = 0; it < 2; it++) {
        int idx = tid + it*256;            // 0..511
        int n = idx >> 3, u = idx & 7;
        int kkl = u >> 2, tg = u & 3;
        int c0 = kkl*16 + 2*tg;
        uint2 val = make_uint2(pkh(sm[(c0    )*65 + n], sm[(c0 + 1)*65 + n]),
                               pkh(sm[(c0 + 8)*65 + n], sm[(c0 + 9)*65 + n]));
        *(uint2*)&dst[n*16 + u*2] = val;
    }
}

// ---------------------------------------------------------------------------
// Kernel 1: fused QKV projection, fp16 m16n8k16 cp.async GEMM.
// grid (32, 12, 2 n-splits); 256 threads (8 warps: 4m x 2n). 2 CTAs/SM.
// 4-stage ring, copy-before-wait, wait<2> (2-deep latency cover).
// ---------------------------------------------------------------------------
#define PXW  (128*20)             // 2560 words: X part (row stride 20)
#define PWW  (3*32*20)            // 1920 words: W part
#define PSTG (PXW + PWW)          // 4480 words per stage
#define PNC  (DIN/32)             // 24 chunks of K=32

__global__ __launch_bounds__(256, 2)
void qkv_proj_kernel() {
    extern __shared__ uint32_t psm[];

    const int tid = threadIdx.x;
    const int wid = tid >> 5, lane = tid & 31;
    const int tg = lane >> 2, tig = lane & 3;
    const int wm = wid >> 1, wn = wid & 1;      // 4m x 2n warps
    const int h = blockIdx.y;
    const int ns = blockIdx.z;
    const int rowblk = blockIdx.x * 128;

    const uint32_t smem_base = (uint32_t)__cvta_generic_to_shared(psm);

    float acc[3][2][2][4];
    #pragma unroll
    for (int m = 0; m < 3; m++)
        #pragma unroll
        for (int i = 0; i < 2; i++)
            #pragma unroll
            for (int j = 0; j < 2; j++)
                #pragma unroll
                for (int r = 0; r < 4; r++) acc[m][i][j][r] = 0.f;

    auto copy_chunk = [&](int kc, int stage) {
        const uint32_t sb = smem_base + stage * (PSTG*4);
        #pragma unroll
        for (int u = 0; u < 4; u++) {
            int idx = tid + u*256;
            if (idx < 512) {
                int r = idx >> 2, cc = idx & 3;
                cpa16(sb + (r*20 + cc*4)*4,
                      g_Xf16 + (size_t)(rowblk + r)*384 + kc*16 + cc*4);
            } else if (idx < 896) {
                int widx = idx - 512;
                int m = widx >> 7, rem = widx & 127;
                int n = rem >> 2, cc = rem & 3;
                cpa16(sb + (PXW + m*640 + n*20 + cc*4)*4,
                      g_Wf16 + ((size_t)((m*HH + h)*24 + kc))*1024
                             + (size_t)(ns*32 + n)*16 + cc*4);
            }
        }
        cpa_commit();
    };

    copy_chunk(0, 0);
    copy_chunk(1, 1);

    for (int kc = 0; kc < PNC; kc++) {
        // write stage (kc+2)&3: prior contents (chunk kc-2) were consumed at
        // iter kc-2 and sealed by the barrier at iter kc-1.
        if (kc + 2 < PNC) copy_chunk(kc + 2, (kc + 2) & 3);
        if      (kc + 2 < PNC) cpa_wait<2>();
        else if (kc + 1 < PNC) cpa_wait<1>();
        else                   cpa_wait<0>();
        __syncthreads();

        const uint32_t* Xs = psm + (kc & 3) * PSTG;
        const uint32_t* Ws = Xs + PXW;

        #pragma unroll
        for (int ks = 0; ks < 2; ks++) {            // 2 k16 steps per chunk
            const int u = ks*4 + tig;
            uint32_t a[2][4];
            #pragma unroll
            for (int ms = 0; ms < 2; ms++) {
                int r0 = wm*32 + ms*16 + tg;
                uint2 lo = *(const uint2*)&Xs[(r0    )*20 + u*2];
                uint2 hi = *(const uint2*)&Xs[(r0 + 8)*20 + u*2];
                a[ms][0] = lo.x; a[ms][1] = hi.x; a[ms][2] = lo.y; a[ms][3] = hi.y;
            }
            #pragma unroll
            for (int m = 0; m < 3; m++) {
                #pragma unroll
                for (int j = 0; j < 2; j++) {
                    int n0 = wn*16 + j*8 + tg;
                    uint2 bv = *(const uint2*)&Ws[m*640 + n0*20 + u*2];
                    #pragma unroll
                    for (int ms = 0; ms < 2; ms++)
                        mma_f16(acc[m][ms][j], a[ms][0], a[ms][1], a[ms][2], a[ms][3],
                                bv.x, bv.y);
                }
            }
        }
    }
    __syncthreads();   // all mma done before smem reuse

    // ------------------- Epilogue -------------------
    const int b = rowblk >> 10;
    const int s0 = rowblk & 1023;
    const size_t base = (((size_t)b*HH + h)*SS);

    // Q: fp32 direct (this CTA's 32 columns; already pre-scaled via Wq)
    #pragma unroll
    for (int ms = 0; ms < 2; ms++) {
        int r0 = s0 + wm*32 + ms*16 + tg;
        #pragma unroll
        for (int j = 0; j < 2; j++) {
            int c0 = ns*32 + wn*16 + j*8 + tig*2;
            #pragma unroll
            for (int half = 0; half < 2; half++) {
                *(float2*)&g_Qf[(base + r0 + half*8)*DH + c0] =
                    make_float2(acc[0][ms][j][half*2], acc[0][ms][j][half*2+1]);
            }
        }
    }

    // K, V: bounce through smem (fp32, stride 36), emit fp16 pair units.
    float* Ksm = (float*)psm;                 // [128][36]
    float* Vsm = (float*)psm + 128*36;        // [128][36]
    #pragma unroll
    for (int ms = 0; ms < 2; ms++) {
        int rl = wm*32 + ms*16 + tg;
        #pragma unroll
        for (int j = 0; j < 2; j++) {
            int c0 = wn*16 + j*8 + tig*2;     // local column
            #pragma unroll
            for (int half = 0; half < 2; half++) {
                *(float2*)&Ksm[(rl + half*8)*36 + c0] =
                    make_float2(acc[1][ms][j][half*2], acc[1][ms][j][half*2+1]);
                *(float2*)&Vsm[(rl + half*8)*36 + c0] =
                    make_float2(acc[2][ms][j][half*2], acc[2][ms][j][half*2+1]);
            }
        }
    }
    __syncthreads();

    // Kf16: per s-row, local kk' in {0,1} (global kk = ns*2+kk'), 4 tig units.
    {
        uint32_t* kf = g_Kf16 + (base + s0)*32;
        #pragma unroll
        for (int u = 0; u < 4; u++) {
            int idx = tid + u*256;            // 0..1023
            int sl = idx >> 3, ul = idx & 7;
            int kkl = ul >> 2, tgu = ul & 3;
            int c0 = kkl*16 + 2*tgu;
            uint2 val = make_uint2(pkh(Ksm[sl*36 + c0    ], Ksm[sl*36 + c0 + 1]),
                                   pkh(Ksm[sl*36 + c0 + 8], Ksm[sl*36 + c0 + 9]));
            int kk = ns*2 + kkl;
            *(uint2*)&kf[(size_t)sl*32 + (kk*4 + tgu)*2] = val;
        }
    }
    // Vf16: per local e, K0 local in [0,8), 4 tig units (pairs over s).
    {
        uint32_t* vf = g_Vf16 + ((size_t)b*HH + h) * (DH*SS/2);
        #pragma unroll
        for (int u = 0; u < 4; u++) {
            int idx = tid + u*256;            // 0..1023
            int el = idx >> 5, rem = idx & 31;
            int K0l = rem >> 2, tgu = rem & 3;
            int sl0 = K0l*16 + 2*tgu;
            uint2 val = make_uint2(pkh(Vsm[(sl0    )*36 + el], Vsm[(sl0 + 1)*36 + el]),
                                   pkh(Vsm[(sl0 + 8)*36 + el], Vsm[(sl0 + 9)*36 + el]));
            int e = ns*32 + el;
            *(uint2*)&vf[(size_t)e*512 + ((s0 >> 4) + K0l)*8 + tgu*2] = val;
        }
    }
}

// ---------------------------------------------------------------------------
// Kernel 2: fp16 tensor-core causal flash attention.
// 128-key mega-stages: one cpa_wait + barrier per TWO 64-key subtiles.
// grid (16, 12, 4); 128 threads; 3-stage ring; 2 CTAs/SM (96KB smem).
// ---------------------------------------------------------------------------
#define SUBW 4096    // words per 64-key subtile: K 2048 + V 2048
#define MSTW (2*SUBW)   // words per mega-stage (128 keys)

__global__ __launch_bounds__(128, 2)
void attn_kernel(float* __restrict__ out) {
    extern __shared__ uint32_t smu[];

    const int mt = gridDim.x - 1 - blockIdx.x;
    const int h = blockIdx.y, b = blockIdx.z;
    const int tid = threadIdx.x, wid = tid >> 5, lane = tid & 31;
    const int tg = lane >> 2, tig = lane & 3;
    const int m0 = mt * 64;
    const int nt = mt + 1;              // # 64-key tiles
    const int nmt = (nt + 1) >> 1;      // # 128-key mega-stages
    const size_t bh = ((size_t)b*HH + h) * SS;
    const float*    gqf = g_Qf + bh*DH;
    const uint32_t* gkf = g_Kf16 + bh*32;
    const uint32_t* gvf = g_Vf16 + ((size_t)b*HH + h) * (DH*SS/2);

    const uint32_t smem_base = (uint32_t)__cvta_generic_to_shared(smu);

    // Q fragments (already scaled by 1/8 in projection): pack to f16x2 pairs.
    uint32_t qa[4][4];
    {
        const int r0 = m0 + wid*16 + tg;
        #pragma unroll
        for (int kk = 0; kk < 4; kk++) {
            float2 lo0 = *(const float2*)&gqf[(size_t)(r0    )*DH + kk*16 + 2*tig];
            float2 lo1 = *(const float2*)&gqf[(size_t)(r0 + 8)*DH + kk*16 + 2*tig];
            float2 hi0 = *(const float2*)&gqf[(size_t)(r0    )*DH + kk*16 + 8 + 2*tig];
            float2 hi1 = *(const float2*)&gqf[(size_t)(r0 + 8)*DH + kk*16 + 8 + 2*tig];
            qa[kk][0] = pkh(lo0.x, lo0.y);
            qa[kk][1] = pkh(lo1.x, lo1.y);
            qa[kk][2] = pkh(hi0.x, hi0.y);
            qa[kk][3] = pkh(hi1.x, hi1.y);
        }
    }

    auto copy_mega = [&](int mtI, int stage) {
        const uint32_t sb = smem_base + stage * (MSTW*4);
        const int kt0 = mtI*2;
        const int nsub = (nt - kt0 >= 2) ? 2 : 1;
        for (int sub = 0; sub < nsub; sub++) {
            const int kt = kt0 + sub;
            const uint32_t sbb = sb + sub*(SUBW*4);
            #pragma unroll
            for (int u = 0; u < 4; u++) {
                int idx = tid + u*128;
                int n = idx >> 3, cc = idx & 7;
                cpa16(sbb + n*128 + (cc ^ (n & 7))*16,
                      gkf + ((size_t)(kt*64 + n)*32 + cc*4));
            }
            #pragma unroll
            for (int u = 0; u < 4; u++) {
                int idx = tid + u*128;
                int e = idx >> 3, cc = idx & 7;
                cpa16(sbb + 2048*4 + e*128 + (cc ^ (e & 7))*16,
                      gvf + ((size_t)e*512 + kt*32 + cc*4));
            }
        }
        cpa_commit();
    };

    float o[8][4];
    #pragma unroll
    for (int j = 0; j < 8; j++)
        #pragma unroll
        for (int i = 0; i < 4; i++) o[j][i] = 0.f;
    float mrow[2] = {-1e30f, -1e30f};
    float lrow[2] = {0.f, 0.f};

    copy_mega(0, 0);
    if (nmt > 1) copy_mega(1, 1);

    for (int mtI = 0; mtI < nmt; mtI++) {
        if (mtI + 1 < nmt) cpa_wait<1>(); else cpa_wait<0>();
        __syncthreads();
        if (mtI + 2 < nmt) copy_mega(mtI + 2, (mtI + 2) % 3);

        #pragma unroll
        for (int sub = 0; sub < 2; sub++) {
            const int kt = mtI*2 + sub;
            if (kt >= nt) break;
            const uint32_t* Kst = smu + (mtI % 3)*MSTW + sub*SUBW;
            const uint32_t* Vst = Kst + 2048;

            float c[8][4];
            #pragma unroll
            for (int j = 0; j < 8; j++)
                #pragma unroll
                for (int i = 0; i < 4; i++) c[j][i] = 0.f;

            // ---- S = Q K^T ----
            #pragma unroll
            for (int kk = 0; kk < 4; kk++) {
                const int u = kk*4 + tig;
                const int cc = u >> 1, half = u & 1;
                #pragma unroll
                for (int j = 0; j < 8; j++) {
                    const int nr = j*8 + tg;
                    uint2 kv = *(const uint2*)&Kst[nr*32 + (cc ^ (nr & 7))*4 + half*2];
                    mma_f16(c[j], qa[kk][0], qa[kk][1], qa[kk][2], qa[kk][3], kv.x, kv.y);
                }
            }

            if (kt == mt) {       // diagonal tile: causal mask
                const int rl0 = wid*16 + tg, rl1 = rl0 + 8;
                #pragma unroll
                for (int j = 0; j < 8; j++) {
                    int c0 = j*8 + 2*tig, c1 = c0 + 1;
                    if (c0 > rl0) c[j][0] = -1e30f;
                    if (c1 > rl0) c[j][1] = -1e30f;
                    if (c0 > rl1) c[j][2] = -1e30f;
                    if (c1 > rl1) c[j][3] = -1e30f;
                }
            }

            float alpha[2];
            #pragma unroll
            for (int h2 = 0; h2 < 2; h2++) {
                float mx = -1e30f;
                #pragma unroll
                for (int j = 0; j < 8; j++) {
                    mx = fmaxf(mx, c[j][h2*2]);
                    mx = fmaxf(mx, c[j][h2*2 + 1]);
                }
                mx = fmaxf(mx, __shfl_xor_sync(0xffffffffu, mx, 1));
                mx = fmaxf(mx, __shfl_xor_sync(0xffffffffu, mx, 2));
                float mnew = fmaxf(mrow[h2], mx);
                float sum = 0.f;
                #pragma unroll
                for (int j = 0; j < 8; j++) {
                    float p0 = __expf(c[j][h2*2]     - mnew);
                    float p1 = __expf(c[j][h2*2 + 1] - mnew);
                    c[j][h2*2]     = p0;
                    c[j][h2*2 + 1] = p1;
                    sum += p0 + p1;
                }
                sum += __shfl_xor_sync(0xffffffffu, sum, 1);
                sum += __shfl_xor_sync(0xffffffffu, sum, 2);
                alpha[h2] = __expf(mrow[h2] - mnew);
                mrow[h2] = mnew;
                lrow[h2] = lrow[h2]*alpha[h2] + sum;
            }

            #pragma unroll
            for (int j = 0; j < 8; j++) {
                o[j][0] *= alpha[0]; o[j][1] *= alpha[0];
                o[j][2] *= alpha[1]; o[j][3] *= alpha[1];
            }

            // ---- O += P V : C-frag pairs ARE the A-frag pairs ----
            #pragma unroll
            for (int K0 = 0; K0 < 4; K0++) {
                uint32_t a0 = pkh(c[2*K0    ][0], c[2*K0    ][1]);
                uint32_t a1 = pkh(c[2*K0    ][2], c[2*K0    ][3]);
                uint32_t a2 = pkh(c[2*K0 + 1][0], c[2*K0 + 1][1]);
                uint32_t a3 = pkh(c[2*K0 + 1][2], c[2*K0 + 1][3]);
                const int u = K0*4 + tig;
                const int cc = u >> 1, half = u & 1;
                #pragma unroll
                for (int jn = 0; jn < 8; jn++) {
                    const int e = jn*8 + tg;
                    uint2 vv = *(const uint2*)&Vst[e*32 + (cc ^ (e & 7))*4 + half*2];
                    mma_f16(o[jn], a0, a1, a2, a3, vv.x, vv.y);
                }
            }
        }
        // mega-stage reuse sealed by the barrier at iteration mtI+2
    }

    const float inv0 = 1.f / lrow[0], inv1 = 1.f / lrow[1];
    const int r0 = m0 + wid*16 + tg;
    #pragma unroll
    for (int j = 0; j < 8; j++) {
        int col = h*DH + j*8 + 2*tig;
        *(float2*)&out[((size_t)b*SS + r0    )*(HH*DH) + col] =
            make_float2(o[j][0]*inv0, o[j][1]*inv0);
        *(float2*)&out[((size_t)b*SS + r0 + 8)*(HH*DH) + col] =
            make_float2(o[j][2]*inv1, o[j][3]*inv1);
    }
}

// ---------------------------------------------------------------------------
extern "C" void kernel_launch(void* const* d_in, const int* in_sizes, int n_in,
                              void* d_out, int out_size) {
    const float* x  = (const float*)d_in[0];
    const float* Wq = (const float*)d_in[1];
    const float* Wk = (const float*)d_in[2];
    const float* Wv = (const float*)d_in[3];
    float* out = (float*)d_out;

    prep_x<<<768, 256>>>(x);
    prep_w<<<dim3(24, HH, 3), 256>>>(Wq, Wk, Wv);

    const int proj_smem = 4 * PSTG * (int)sizeof(uint32_t);        // 71,680 B
    cudaFuncSetAttribute(qkv_proj_kernel, cudaFuncAttributeMaxDynamicSharedMemorySize,
                         proj_smem);
    qkv_proj_kernel<<<dim3((BB*SS)/128, HH, 2), 256, proj_smem>>>();

    const int attn_smem = 3 * MSTW * (int)sizeof(uint32_t);        // 98,304 B
    cudaFuncSetAttribute(attn_kernel, cudaFuncAttributeMaxDynamicSharedMemorySize,
                         attn_smem);
    attn_kernel<<<dim3(SS/64, HH, BB), 128, attn_smem>>>(out);
}

// round 15
// speedup vs baseline: 1.0134x; 1.0134x over previous
#include <cuda_runtime.h>
#include <cuda_fp16.h>
#include <cstdint>

// Problem constants
#define BB   4
#define SS   1024
#define DIN  768
#define HH   12
#define DH   64
#define WWRD (HH*DIN*DH)

// Scratch (device globals; no allocs allowed). fp16 pair-unit layouts:
// unit(row, kk, tig) = { f16x2(v[16kk+2tig], v[16kk+2tig+1]),
//                        f16x2(v[16kk+8+2tig], v[16kk+9+2tig]) }   (8 bytes)
__device__ __align__(16) uint32_t g_Xf16[BB*SS*DIN/2];        // [row][kk48][tig4]
__device__ __align__(16) uint32_t g_Wf16[3*WWRD/2];           // [(m,h)][kc24][n64][u8]
__device__ __align__(16) float    g_Qf  [BB*HH*SS*DH];        // fp32 [b,h,s,e] (pre-scaled 1/8)
__device__ __align__(16) uint32_t g_Kf16[(size_t)BB*HH*SS*DH/2]; // [s][u16][2w] per (b,h)
__device__ __align__(16) uint32_t g_Vf16[(size_t)BB*HH*DH*SS/2]; // [e][K0*4+tig][2w]

// ---------------------------------------------------------------------------
// helpers
// ---------------------------------------------------------------------------
__device__ __forceinline__ uint32_t pkh(float a, float b) {
    __half2 h = __floats2half2_rn(a, b);
    return *reinterpret_cast<uint32_t*>(&h);
}

__device__ __forceinline__ void mma_f16(float c[4],
                                        uint32_t a0, uint32_t a1, uint32_t a2, uint32_t a3,
                                        uint32_t b0, uint32_t b1) {
    asm volatile(
        "mma.sync.aligned.m16n8k16.row.col.f32.f16.f16.f32 "
        "{%0,%1,%2,%3}, {%4,%5,%6,%7}, {%8,%9}, {%0,%1,%2,%3};"
        : "+f"(c[0]), "+f"(c[1]), "+f"(c[2]), "+f"(c[3])
        : "r"(a0), "r"(a1), "r"(a2), "r"(a3), "r"(b0), "r"(b1));
}

__device__ __forceinline__ void cpa16(uint32_t smem_addr, const void* gptr) {
    asm volatile("cp.async.cg.shared.global [%0], [%1], 16;"
                 :: "r"(smem_addr), "l"(gptr));
}
__device__ __forceinline__ void cpa_commit() {
    asm volatile("cp.async.commit_group;");
}
template <int N>
__device__ __forceinline__ void cpa_wait() {
    asm volatile("cp.async.wait_group %0;" :: "n"(N));
}

// ---------------------------------------------------------------------------
// Kernel 0a: x fp32 -> fp16 pair units. One (row, kk16) per thread.
// ---------------------------------------------------------------------------
__global__ __launch_bounds__(256)
void prep_x(const float* __restrict__ x) {
    int idx = blockIdx.x*256 + threadIdx.x;      // 0..196607
    int row = idx / 48, kk = idx % 48;
    const float4* src = (const float4*)(x + (size_t)row*DIN + kk*16);
    float4 v0 = src[0], v1 = src[1], v2 = src[2], v3 = src[3];
    float f[16] = {v0.x,v0.y,v0.z,v0.w, v1.x,v1.y,v1.z,v1.w,
                   v2.x,v2.y,v2.z,v2.w, v3.x,v3.y,v3.z,v3.w};
    uint32_t w[8];
    #pragma unroll
    for (int tg = 0; tg < 4; tg++) {
        w[tg*2]   = pkh(f[2*tg],     f[2*tg + 1]);
        w[tg*2+1] = pkh(f[8 + 2*tg], f[9 + 2*tg]);
    }
    uint4* dst = (uint4*)&g_Xf16[(size_t)row*384 + kk*8];
    dst[0] = *(uint4*)&w[0];
    dst[1] = *(uint4*)&w[4];
}

// ---------------------------------------------------------------------------
// Kernel 0b: W [h][k][n] fp32 -> fp16 pair units [(m,h)][kc][n][u8].
// Wq is pre-scaled by 0.125 (exact) so attention scores need no scaling.
// grid (24 kc, 12 h, 3 m), 256 threads, smem bounce.
// ---------------------------------------------------------------------------
__global__ __launch_bounds__(256)
void prep_w(const float* __restrict__ Wq, const float* __restrict__ Wk,
            const float* __restrict__ Wv) {
    __shared__ float sm[32*65];
    const int kc = blockIdx.x, h = blockIdx.y, m = blockIdx.z;
    const int tid = threadIdx.x;
    const float scale = (m == 0) ? 0.125f : 1.0f;
    const float* src = ((m == 0) ? Wq : (m == 1) ? Wk : Wv)
                       + (size_t)h*DIN*DH + (size_t)kc*32*DH;
    #pragma unroll
    for (int it = 0; it < 8; it++) {
        int idx = tid + it*256;            // 0..2047
        int k = idx >> 6, n = idx & 63;
        sm[k*65 + n] = scale * src[k*64 + n];
    }
    __syncthreads();
    uint32_t* dst = g_Wf16 + ((size_t)((m*HH + h)*24 + kc))*1024;  // 64n x 16w
    #pragma unroll
    for (int it = 0; it < 2; it++) {
        int idx = tid + it*256;            // 0..511
        int n = idx >> 3, u = idx & 7;
        int kkl = u >> 2, tg = u & 3;
        int c0 = kkl*16 + 2*tg;
        uint2 val = make_uint2(pkh(sm[(c0    )*65 + n], sm[(c0 + 1)*65 + n]),
                               pkh(sm[(c0 + 8)*65 + n], sm[(c0 + 9)*65 + n]));
        *(uint2*)&dst[n*16 + u*2] = val;
    }
}

// ---------------------------------------------------------------------------
// Kernel 1: fused QKV projection, fp16 m16n8k16 cp.async GEMM.
// grid (32, 12, 2 n-splits); 256 threads (8 warps: 4m x 2n). 2 CTAs/SM.
// 4-stage ring, copy-before-wait, wait<2>.
// ---------------------------------------------------------------------------
#define PXW  (128*20)             // 2560 words: X part (row stride 20)
#define PWW  (3*32*20)            // 1920 words: W part
#define PSTG (PXW + PWW)          // 4480 words per stage
#define PNC  (DIN/32)             // 24 chunks of K=32

__global__ __launch_bounds__(256, 2)
void qkv_proj_kernel() {
    extern __shared__ uint32_t psm[];

    const int tid = threadIdx.x;
    const int wid = tid >> 5, lane = tid & 31;
    const int tg = lane >> 2, tig = lane & 3;
    const int wm = wid >> 1, wn = wid & 1;      // 4m x 2n warps
    const int h = blockIdx.y;
    const int ns = blockIdx.z;
    const int rowblk = blockIdx.x * 128;

    const uint32_t smem_base = (uint32_t)__cvta_generic_to_shared(psm);

    float acc[3][2][2][4];
    #pragma unroll
    for (int m = 0; m < 3; m++)
        #pragma unroll
        for (int i = 0; i < 2; i++)
            #pragma unroll
            for (int j = 0; j < 2; j++)
                #pragma unroll
                for (int r = 0; r < 4; r++) acc[m][i][j][r] = 0.f;

    auto copy_chunk = [&](int kc, int stage) {
        const uint32_t sb = smem_base + stage * (PSTG*4);
        #pragma unroll
        for (int u = 0; u < 4; u++) {
            int idx = tid + u*256;
            if (idx < 512) {
                int r = idx >> 2, cc = idx & 3;
                cpa16(sb + (r*20 + cc*4)*4,
                      g_Xf16 + (size_t)(rowblk + r)*384 + kc*16 + cc*4);
            } else if (idx < 896) {
                int widx = idx - 512;
                int m = widx >> 7, rem = widx & 127;
                int n = rem >> 2, cc = rem & 3;
                cpa16(sb + (PXW + m*640 + n*20 + cc*4)*4,
                      g_Wf16 + ((size_t)((m*HH + h)*24 + kc))*1024
                             + (size_t)(ns*32 + n)*16 + cc*4);
            }
        }
        cpa_commit();
    };

    copy_chunk(0, 0);
    copy_chunk(1, 1);

    for (int kc = 0; kc < PNC; kc++) {
        // write stage (kc+2)&3: prior contents (chunk kc-2) consumed at
        // iter kc-2 and sealed by the barrier at iter kc-1.
        if (kc + 2 < PNC) copy_chunk(kc + 2, (kc + 2) & 3);
        if      (kc + 2 < PNC) cpa_wait<2>();
        else if (kc + 1 < PNC) cpa_wait<1>();
        else                   cpa_wait<0>();
        __syncthreads();

        const uint32_t* Xs = psm + (kc & 3) * PSTG;
        const uint32_t* Ws = Xs + PXW;

        #pragma unroll
        for (int ks = 0; ks < 2; ks++) {            // 2 k16 steps per chunk
            const int u = ks*4 + tig;
            uint32_t a[2][4];
            #pragma unroll
            for (int ms = 0; ms < 2; ms++) {
                int r0 = wm*32 + ms*16 + tg;
                uint2 lo = *(const uint2*)&Xs[(r0    )*20 + u*2];
                uint2 hi = *(const uint2*)&Xs[(r0 + 8)*20 + u*2];
                a[ms][0] = lo.x; a[ms][1] = hi.x; a[ms][2] = lo.y; a[ms][3] = hi.y;
            }
            #pragma unroll
            for (int m = 0; m < 3; m++) {
                #pragma unroll
                for (int j = 0; j < 2; j++) {
                    int n0 = wn*16 + j*8 + tg;
                    uint2 bv = *(const uint2*)&Ws[m*640 + n0*20 + u*2];
                    #pragma unroll
                    for (int ms = 0; ms < 2; ms++)
                        mma_f16(acc[m][ms][j], a[ms][0], a[ms][1], a[ms][2], a[ms][3],
                                bv.x, bv.y);
                }
            }
        }
    }
    __syncthreads();   // all mma done before smem reuse

    // ------------------- Epilogue -------------------
    const int b = rowblk >> 10;
    const int s0 = rowblk & 1023;
    const size_t base = (((size_t)b*HH + h)*SS);

    // Q: fp32 direct (this CTA's 32 columns; already pre-scaled via Wq)
    #pragma unroll
    for (int ms = 0; ms < 2; ms++) {
        int r0 = s0 + wm*32 + ms*16 + tg;
        #pragma unroll
        for (int j = 0; j < 2; j++) {
            int c0 = ns*32 + wn*16 + j*8 + tig*2;
            #pragma unroll
            for (int half = 0; half < 2; half++) {
                *(float2*)&g_Qf[(base + r0 + half*8)*DH + c0] =
                    make_float2(acc[0][ms][j][half*2], acc[0][ms][j][half*2+1]);
            }
        }
    }

    // K, V: bounce through smem (fp32, stride 36), emit fp16 pair units.
    float* Ksm = (float*)psm;                 // [128][36]
    float* Vsm = (float*)psm + 128*36;        // [128][36]
    #pragma unroll
    for (int ms = 0; ms < 2; ms++) {
        int rl = wm*32 + ms*16 + tg;
        #pragma unroll
        for (int j = 0; j < 2; j++) {
            int c0 = wn*16 + j*8 + tig*2;     // local column
            #pragma unroll
            for (int half = 0; half < 2; half++) {
                *(float2*)&Ksm[(rl + half*8)*36 + c0] =
                    make_float2(acc[1][ms][j][half*2], acc[1][ms][j][half*2+1]);
                *(float2*)&Vsm[(rl + half*8)*36 + c0] =
                    make_float2(acc[2][ms][j][half*2], acc[2][ms][j][half*2+1]);
            }
        }
    }
    __syncthreads();

    // Kf16: per s-row, local kk' in {0,1} (global kk = ns*2+kk'), 4 tig units.
    {
        uint32_t* kf = g_Kf16 + (base + s0)*32;
        #pragma unroll
        for (int u = 0; u < 4; u++) {
            int idx = tid + u*256;            // 0..1023
            int sl = idx >> 3, ul = idx & 7;
            int kkl = ul >> 2, tgu = ul & 3;
            int c0 = kkl*16 + 2*tgu;
            uint2 val = make_uint2(pkh(Ksm[sl*36 + c0    ], Ksm[sl*36 + c0 + 1]),
                                   pkh(Ksm[sl*36 + c0 + 8], Ksm[sl*36 + c0 + 9]));
            int kk = ns*2 + kkl;
            *(uint2*)&kf[(size_t)sl*32 + (kk*4 + tgu)*2] = val;
        }
    }
    // Vf16: per local e, K0 local in [0,8), 4 tig units (pairs over s).
    {
        uint32_t* vf = g_Vf16 + ((size_t)b*HH + h) * (DH*SS/2);
        #pragma unroll
        for (int u = 0; u < 4; u++) {
            int idx = tid + u*256;            // 0..1023
            int el = idx >> 5, rem = idx & 31;
            int K0l = rem >> 2, tgu = rem & 3;
            int sl0 = K0l*16 + 2*tgu;
            uint2 val = make_uint2(pkh(Vsm[(sl0    )*36 + el], Vsm[(sl0 + 1)*36 + el]),
                                   pkh(Vsm[(sl0 + 8)*36 + el], Vsm[(sl0 + 9)*36 + el]));
            int e = ns*32 + el;
            *(uint2*)&vf[(size_t)e*512 + ((s0 >> 4) + K0l)*8 + tgu*2] = val;
        }
    }
}

// ---------------------------------------------------------------------------
// Kernel 2: fp16 tensor-core causal flash attention (R13 structure).
// 64-key stages, 3-stage ring, 1 barrier/tile. 3 CTAs/SM: regs=160 fits the
// (128,3) limit of 170 with no spills; smem 3x48KB = 144KB <= 228KB.
// grid (16, 12, 4); 128 threads.
// ---------------------------------------------------------------------------
#define STW 4096     // words per stage: K 2048 + V 2048 (16KB)

__global__ __launch_bounds__(128, 3)
void attn_kernel(float* __restrict__ out) {
    extern __shared__ uint32_t smu[];

    const int mt = gridDim.x - 1 - blockIdx.x;
    const int h = blockIdx.y, b = blockIdx.z;
    const int tid = threadIdx.x, wid = tid >> 5, lane = tid & 31;
    const int tg = lane >> 2, tig = lane & 3;
    const int m0 = mt * 64;
    const size_t bh = ((size_t)b*HH + h) * SS;
    const float*    gqf = g_Qf + bh*DH;
    const uint32_t* gkf = g_Kf16 + bh*32;
    const uint32_t* gvf = g_Vf16 + ((size_t)b*HH + h) * (DH*SS/2);

    const uint32_t smem_base = (uint32_t)__cvta_generic_to_shared(smu);

    // Q fragments (already scaled by 1/8 in projection): pack to f16x2 pairs.
    uint32_t qa[4][4];
    {
        const int r0 = m0 + wid*16 + tg;
        #pragma unroll
        for (int kk = 0; kk < 4; kk++) {
            float2 lo0 = *(const float2*)&gqf[(size_t)(r0    )*DH + kk*16 + 2*tig];
            float2 lo1 = *(const float2*)&gqf[(size_t)(r0 + 8)*DH + kk*16 + 2*tig];
            float2 hi0 = *(const float2*)&gqf[(size_t)(r0    )*DH + kk*16 + 8 + 2*tig];
            float2 hi1 = *(const float2*)&gqf[(size_t)(r0 + 8)*DH + kk*16 + 8 + 2*tig];
            qa[kk][0] = pkh(lo0.x, lo0.y);
            qa[kk][1] = pkh(lo1.x, lo1.y);
            qa[kk][2] = pkh(hi0.x, hi0.y);
            qa[kk][3] = pkh(hi1.x, hi1.y);
        }
    }

    auto copy_tile = [&](int kt, int stage) {
        const uint32_t sb = smem_base + stage * (STW*4);
        #pragma unroll
        for (int u = 0; u < 4; u++) {
            int idx = tid + u*128;
            int n = idx >> 3, cc = idx & 7;
            cpa16(sb + n*128 + (cc ^ (n & 7))*16,
                  gkf + ((size_t)(kt*64 + n)*32 + cc*4));
        }
        #pragma unroll
        for (int u = 0; u < 4; u++) {
            int idx = tid + u*128;
            int e = idx >> 3, cc = idx & 7;
            cpa16(sb + 2048*4 + e*128 + (cc ^ (e & 7))*16,
                  gvf + ((size_t)e*512 + kt*32 + cc*4));
        }
        cpa_commit();
    };

    float o[8][4];
    #pragma unroll
    for (int j = 0; j < 8; j++)
        #pragma unroll
        for (int i = 0; i < 4; i++) o[j][i] = 0.f;
    float mrow[2] = {-1e30f, -1e30f};
    float lrow[2] = {0.f, 0.f};

    copy_tile(0, 0);
    if (mt >= 1) copy_tile(1, 1);

    for (int kt = 0; kt <= mt; kt++) {
        if (kt + 1 <= mt) cpa_wait<1>(); else cpa_wait<0>();
        __syncthreads();
        if (kt + 2 <= mt) copy_tile(kt + 2, (kt + 2) % 3);

        const uint32_t* Kst = smu + (kt % 3)*STW;
        const uint32_t* Vst = Kst + 2048;

        float c[8][4];
        #pragma unroll
        for (int j = 0; j < 8; j++)
            #pragma unroll
            for (int i = 0; i < 4; i++) c[j][i] = 0.f;

        // ---- S = Q K^T : 4 k16-steps x 8 n-blocks ----
        #pragma unroll
        for (int kk = 0; kk < 4; kk++) {
            const int u = kk*4 + tig;
            const int cc = u >> 1, half = u & 1;
            #pragma unroll
            for (int j = 0; j < 8; j++) {
                const int nr = j*8 + tg;
                uint2 kv = *(const uint2*)&Kst[nr*32 + (cc ^ (nr & 7))*4 + half*2];
                mma_f16(c[j], qa[kk][0], qa[kk][1], qa[kk][2], qa[kk][3], kv.x, kv.y);
            }
        }

        if (kt == mt) {       // diagonal tile: causal mask
            const int rl0 = wid*16 + tg, rl1 = rl0 + 8;
            #pragma unroll
            for (int j = 0; j < 8; j++) {
                int c0 = j*8 + 2*tig, c1 = c0 + 1;
                if (c0 > rl0) c[j][0] = -1e30f;
                if (c1 > rl0) c[j][1] = -1e30f;
                if (c0 > rl1) c[j][2] = -1e30f;
                if (c1 > rl1) c[j][3] = -1e30f;
            }
        }

        float alpha[2];
        #pragma unroll
        for (int h2 = 0; h2 < 2; h2++) {
            float mx = -1e30f;
            #pragma unroll
            for (int j = 0; j < 8; j++) {
                mx = fmaxf(mx, c[j][h2*2]);
                mx = fmaxf(mx, c[j][h2*2 + 1]);
            }
            mx = fmaxf(mx, __shfl_xor_sync(0xffffffffu, mx, 1));
            mx = fmaxf(mx, __shfl_xor_sync(0xffffffffu, mx, 2));
            float mnew = fmaxf(mrow[h2], mx);
            float sum = 0.f;
            #pragma unroll
            for (int j = 0; j < 8; j++) {
                float p0 = __expf(c[j][h2*2]     - mnew);
                float p1 = __expf(c[j][h2*2 + 1] - mnew);
                c[j][h2*2]     = p0;
                c[j][h2*2 + 1] = p1;
                sum += p0 + p1;
            }
            sum += __shfl_xor_sync(0xffffffffu, sum, 1);
            sum += __shfl_xor_sync(0xffffffffu, sum, 2);
            alpha[h2] = __expf(mrow[h2] - mnew);
            mrow[h2] = mnew;
            lrow[h2] = lrow[h2]*alpha[h2] + sum;
        }

        #pragma unroll
        for (int j = 0; j < 8; j++) {
            o[j][0] *= alpha[0]; o[j][1] *= alpha[0];
            o[j][2] *= alpha[1]; o[j][3] *= alpha[1];
        }

        // ---- O += P V : C-frag pairs ARE the A-frag pairs (no shuffles) ----
        #pragma unroll
        for (int K0 = 0; K0 < 4; K0++) {
            uint32_t a0 = pkh(c[2*K0    ][0], c[2*K0    ][1]);
            uint32_t a1 = pkh(c[2*K0    ][2], c[2*K0    ][3]);
            uint32_t a2 = pkh(c[2*K0 + 1][0], c[2*K0 + 1][1]);
            uint32_t a3 = pkh(c[2*K0 + 1][2], c[2*K0 + 1][3]);
            const int u = K0*4 + tig;
            const int cc = u >> 1, half = u & 1;
            #pragma unroll
            for (int jn = 0; jn < 8; jn++) {
                const int e = jn*8 + tg;
                uint2 vv = *(const uint2*)&Vst[e*32 + (cc ^ (e & 7))*4 + half*2];
                mma_f16(o[jn], a0, a1, a2, a3, vv.x, vv.y);
            }
        }
        // stage reuse sealed by the barrier at iteration kt+2
    }

    const float inv0 = 1.f / lrow[0], inv1 = 1.f / lrow[1];
    const int r0 = m0 + wid*16 + tg;
    #pragma unroll
    for (int j = 0; j < 8; j++) {
        int col = h*DH + j*8 + 2*tig;
        *(float2*)&out[((size_t)b*SS + r0    )*(HH*DH) + col] =
            make_float2(o[j][0]*inv0, o[j][1]*inv0);
        *(float2*)&out[((size_t)b*SS + r0 + 8)*(HH*DH) + col] =
            make_float2(o[j][2]*inv1, o[j][3]*inv1);
    }
}

// ---------------------------------------------------------------------------
extern "C" void kernel_launch(void* const* d_in, const int* in_sizes, int n_in,
                              void* d_out, int out_size) {
    const float* x  = (const float*)d_in[0];
    const float* Wq = (const float*)d_in[1];
    const float* Wk = (const float*)d_in[2];
    const float* Wv = (const float*)d_in[3];
    float* out = (float*)d_out;

    prep_x<<<768, 256>>>(x);
    prep_w<<<dim3(24, HH, 3), 256>>>(Wq, Wk, Wv);

    const int proj_smem = 4 * PSTG * (int)sizeof(uint32_t);        // 71,680 B
    cudaFuncSetAttribute(qkv_proj_kernel, cudaFuncAttributeMaxDynamicSharedMemorySize,
                         proj_smem);
    qkv_proj_kernel<<<dim3((BB*SS)/128, HH, 2), 256, proj_smem>>>();

    const int attn_smem = 3 * STW * (int)sizeof(uint32_t);         // 49,152 B
    cudaFuncSetAttribute(attn_kernel, cudaFuncAttributeMaxDynamicSharedMemorySize,
                         attn_smem);
    attn_kernel<<<dim3(SS/64, HH, BB), 128, attn_smem>>>(out);
}

// round 16
// speedup vs baseline: 1.2928x; 1.2757x over previous
#include <cuda_runtime.h>
#include <cuda_fp16.h>
#include <cstdint>

// Problem constants
#define BB   4
#define SS   1024
#define DIN  768
#define HH   12
#define DH   64
#define WWRD (HH*DIN*DH)

// fp16 pair-unit: unit(row, kk, tig) = { f16x2(v[16kk+2tig], v[16kk+2tig+1]),
//                                        f16x2(v[16kk+8+2tig], v[16kk+9+2tig]) }
__device__ __align__(16) uint32_t g_Xf16[BB*SS*DIN/2];        // [row][u192] (k-linear)
__device__ __align__(16) uint32_t g_Wf16[3*WWRD/2];           // [(m,h)][kc12][n64][u16]
__device__ __align__(16) float    g_Qf  [BB*HH*SS*DH];        // fp32 (pre-scaled 1/8 via Wq)
__device__ __align__(16) uint32_t g_Kf16[(size_t)BB*HH*SS*DH/2]; // [s][u16][2w] per (b,h)
__device__ __align__(16) uint32_t g_Vf16[(size_t)BB*HH*DH*SS/2]; // [e][u16 per 64-s][2w]

// ---------------------------------------------------------------------------
// helpers
// ---------------------------------------------------------------------------
__device__ __forceinline__ uint32_t pkh(float a, float b) {
    __half2 h = __floats2half2_rn(a, b);
    return *reinterpret_cast<uint32_t*>(&h);
}

__device__ __forceinline__ void mma_f16(float c[4],
                                        uint32_t a0, uint32_t a1, uint32_t a2, uint32_t a3,
                                        uint32_t b0, uint32_t b1) {
    asm volatile(
        "mma.sync.aligned.m16n8k16.row.col.f32.f16.f16.f32 "
        "{%0,%1,%2,%3}, {%4,%5,%6,%7}, {%8,%9}, {%0,%1,%2,%3};"
        : "+f"(c[0]), "+f"(c[1]), "+f"(c[2]), "+f"(c[3])
        : "r"(a0), "r"(a1), "r"(a2), "r"(a3), "r"(b0), "r"(b1));
}

__device__ __forceinline__ void cpa16(uint32_t smem_addr, const void* gptr) {
    asm volatile("cp.async.cg.shared.global [%0], [%1], 16;"
                 :: "r"(smem_addr), "l"(gptr));
}
__device__ __forceinline__ void cpa_commit() {
    asm volatile("cp.async.commit_group;");
}
template <int N>
__device__ __forceinline__ void cpa_wait() {
    asm volatile("cp.async.wait_group %0;" :: "n"(N));
}

// ---------------------------------------------------------------------------
// Kernel 0a: x fp32 -> fp16 pair units (k-linear). One (row, kk16) per thread.
// ---------------------------------------------------------------------------
__global__ __launch_bounds__(256)
void prep_x(const float* __restrict__ x) {
    int idx = blockIdx.x*256 + threadIdx.x;      // 0..196607
    int row = idx / 48, kk = idx % 48;
    const float4* src = (const float4*)(x + (size_t)row*DIN + kk*16);
    float4 v0 = src[0], v1 = src[1], v2 = src[2], v3 = src[3];
    float f[16] = {v0.x,v0.y,v0.z,v0.w, v1.x,v1.y,v1.z,v1.w,
                   v2.x,v2.y,v2.z,v2.w, v3.x,v3.y,v3.z,v3.w};
    uint32_t w[8];
    #pragma unroll
    for (int tg = 0; tg < 4; tg++) {
        w[tg*2]   = pkh(f[2*tg],     f[2*tg + 1]);
        w[tg*2+1] = pkh(f[8 + 2*tg], f[9 + 2*tg]);
    }
    uint4* dst = (uint4*)&g_Xf16[(size_t)row*384 + kk*8];
    dst[0] = *(uint4*)&w[0];
    dst[1] = *(uint4*)&w[4];
}

// ---------------------------------------------------------------------------
// Kernel 0b: W -> fp16 pair units [(m,h)][kc12][n64][u16]. Wq pre-scaled 1/8.
// grid (24 kc32, 12 h, 3 m), 256 threads, smem bounce.
// ---------------------------------------------------------------------------
__global__ __launch_bounds__(256)
void prep_w(const float* __restrict__ Wq, const float* __restrict__ Wk,
            const float* __restrict__ Wv) {
    __shared__ float sm[32*65];
    const int kc = blockIdx.x, h = blockIdx.y, m = blockIdx.z;
    const int tid = threadIdx.x;
    const float scale = (m == 0) ? 0.125f : 1.0f;
    const float* src = ((m == 0) ? Wq : (m == 1) ? Wk : Wv)
                       + (size_t)h*DIN*DH + (size_t)kc*32*DH;
    #pragma unroll
    for (int it = 0; it < 8; it++) {
        int idx = tid + it*256;            // 0..2047
        int k = idx >> 6, n = idx & 63;
        sm[k*65 + n] = scale * src[k*64 + n];
    }
    __syncthreads();
    const int kc12 = kc >> 1, khalf = kc & 1;
    uint32_t* dst = g_Wf16 + ((size_t)((m*HH + h)*12 + kc12))*2048;  // 64n x 32w
    #pragma unroll
    for (int it = 0; it < 2; it++) {
        int idx = tid + it*256;            // 0..511
        int n = idx >> 3, u = idx & 7;     // local unit within this kc32
        int kkl = u >> 2, tg = u & 3;
        int c0 = kkl*16 + 2*tg;
        uint2 val = make_uint2(pkh(sm[(c0    )*65 + n], sm[(c0 + 1)*65 + n]),
                               pkh(sm[(c0 + 8)*65 + n], sm[(c0 + 9)*65 + n]));
        *(uint2*)&dst[n*32 + (khalf*8 + u)*2] = val;
    }
}

// ---------------------------------------------------------------------------
// Kernel 1: fused QKV projection, fp16 m16n8k16 cp.async GEMM.
// grid (32, 12, 2 n-splits); 256 threads (8 warps: 4m x 2n). 2 CTAs/SM.
// K=64 chunks (12 iters, half the barriers). Unit-swizzled smem:
// slot(u, row) = u ^ ((row&3)<<2), stride 32 -> conflict-free LDS.64.
// ---------------------------------------------------------------------------
#define PXW  (128*32)             // 4096 words: X part
#define PWW  (3*32*32)            // 3072 words: W part (3 mats x 32 n x 32 w)
#define PSTG (PXW + PWW)          // 7168 words per stage (28.7KB)
#define PNC  (DIN/64)             // 12 chunks of K=64

__global__ __launch_bounds__(256, 2)
void qkv_proj_kernel() {
    extern __shared__ uint32_t psm[];

    const int tid = threadIdx.x;
    const int wid = tid >> 5, lane = tid & 31;
    const int tg = lane >> 2, tig = lane & 3;
    const int wm = wid >> 1, wn = wid & 1;      // 4m x 2n warps
    const int h = blockIdx.y;
    const int ns = blockIdx.z;
    const int rowblk = blockIdx.x * 128;

    const uint32_t smem_base = (uint32_t)__cvta_generic_to_shared(psm);

    float acc[3][2][2][4];
    #pragma unroll
    for (int m = 0; m < 3; m++)
        #pragma unroll
        for (int i = 0; i < 2; i++)
            #pragma unroll
            for (int j = 0; j < 2; j++)
                #pragma unroll
                for (int r = 0; r < 4; r++) acc[m][i][j][r] = 0.f;

    auto copy_chunk = [&](int kc, int stage) {
        const uint32_t sb = smem_base + stage * (PSTG*4);
        #pragma unroll
        for (int u = 0; u < 7; u++) {
            int idx = tid + u*256;           // 0..1791
            if (idx < 1024) {                // X: 128 rows x 8 16B-chunks
                int r = idx >> 3, cc = idx & 7;
                int slot = (2*cc) ^ ((r & 3) << 2);
                cpa16(sb + (r*32 + slot*2)*4,
                      g_Xf16 + (size_t)(rowblk + r)*384 + kc*32 + cc*4);
            } else {                         // W: 3 mats x 32 n x 8 chunks
                int widx = idx - 1024;
                int m = widx >> 8, rem = widx & 255;
                int n = rem >> 3, cc = rem & 7;
                int slot = (2*cc) ^ ((n & 3) << 2);
                cpa16(sb + (PXW + m*1024 + n*32 + slot*2)*4,
                      g_Wf16 + ((size_t)((m*HH + h)*12 + kc))*2048
                             + (size_t)(ns*32 + n)*32 + cc*4);
            }
        }
        cpa_commit();
    };

    copy_chunk(0, 0);
    copy_chunk(1, 1);

    for (int kc = 0; kc < PNC; kc++) {
        if (kc + 1 < PNC) cpa_wait<1>(); else cpa_wait<0>();
        __syncthreads();
        if (kc + 2 < PNC) copy_chunk(kc + 2, (kc + 2) % 3);

        const uint32_t* Xs = psm + (kc % 3) * PSTG;
        const uint32_t* Ws = Xs + PXW;

        #pragma unroll
        for (int ks = 0; ks < 4; ks++) {            // 4 k16 steps per chunk
            const int u = ks*4 + tig;
            const int slot = u ^ ((tg & 3) << 2);   // rows r: r&3 == tg&3
            uint32_t a[2][4];
            #pragma unroll
            for (int ms = 0; ms < 2; ms++) {
                int r0 = wm*32 + ms*16 + tg;
                uint2 lo = *(const uint2*)&Xs[(r0    )*32 + slot*2];
                uint2 hi = *(const uint2*)&Xs[(r0 + 8)*32 + slot*2];
                a[ms][0] = lo.x; a[ms][1] = hi.x; a[ms][2] = lo.y; a[ms][3] = hi.y;
            }
            #pragma unroll
            for (int m = 0; m < 3; m++) {
                #pragma unroll
                for (int j = 0; j < 2; j++) {
                    int n0 = wn*16 + j*8 + tg;
                    uint2 bv = *(const uint2*)&Ws[m*1024 + n0*32 + slot*2];
                    #pragma unroll
                    for (int ms = 0; ms < 2; ms++)
                        mma_f16(acc[m][ms][j], a[ms][0], a[ms][1], a[ms][2], a[ms][3],
                                bv.x, bv.y);
                }
            }
        }
    }
    __syncthreads();   // all mma done before smem reuse

    // ------------------- Epilogue -------------------
    const int b = rowblk >> 10;
    const int s0 = rowblk & 1023;
    const size_t base = (((size_t)b*HH + h)*SS);

    // Q: fp32 direct (this CTA's 32 columns)
    #pragma unroll
    for (int ms = 0; ms < 2; ms++) {
        int r0 = s0 + wm*32 + ms*16 + tg;
        #pragma unroll
        for (int j = 0; j < 2; j++) {
            int c0 = ns*32 + wn*16 + j*8 + tig*2;
            #pragma unroll
            for (int half = 0; half < 2; half++) {
                *(float2*)&g_Qf[(base + r0 + half*8)*DH + c0] =
                    make_float2(acc[0][ms][j][half*2], acc[0][ms][j][half*2+1]);
            }
        }
    }

    // K, V: bounce through smem (fp32, stride 36), emit fp16 pair units.
    float* Ksm = (float*)psm;                 // [128][36]
    float* Vsm = (float*)psm + 128*36;        // [128][36]
    #pragma unroll
    for (int ms = 0; ms < 2; ms++) {
        int rl = wm*32 + ms*16 + tg;
        #pragma unroll
        for (int j = 0; j < 2; j++) {
            int c0 = wn*16 + j*8 + tig*2;     // local column
            #pragma unroll
            for (int half = 0; half < 2; half++) {
                *(float2*)&Ksm[(rl + half*8)*36 + c0] =
                    make_float2(acc[1][ms][j][half*2], acc[1][ms][j][half*2+1]);
                *(float2*)&Vsm[(rl + half*8)*36 + c0] =
                    make_float2(acc[2][ms][j][half*2], acc[2][ms][j][half*2+1]);
            }
        }
    }
    __syncthreads();

    // Kf16: per s-row, local kk' in {0,1} (global kk = ns*2+kk'), 4 tig units.
    {
        uint32_t* kf = g_Kf16 + (base + s0)*32;
        #pragma unroll
        for (int u = 0; u < 4; u++) {
            int idx = tid + u*256;            // 0..1023
            int sl = idx >> 3, ul = idx & 7;
            int kkl = ul >> 2, tgu = ul & 3;
            int c0 = kkl*16 + 2*tgu;
            uint2 val = make_uint2(pkh(Ksm[sl*36 + c0    ], Ksm[sl*36 + c0 + 1]),
                                   pkh(Ksm[sl*36 + c0 + 8], Ksm[sl*36 + c0 + 9]));
            int kk = ns*2 + kkl;
            *(uint2*)&kf[(size_t)sl*32 + (kk*4 + tgu)*2] = val;
        }
    }
    // Vf16: per local e, K0 local in [0,8), 4 tig units (pairs over s).
    {
        uint32_t* vf = g_Vf16 + ((size_t)b*HH + h) * (DH*SS/2);
        #pragma unroll
        for (int u = 0; u < 4; u++) {
            int idx = tid + u*256;            // 0..1023
            int el = idx >> 5, rem = idx & 31;
            int K0l = rem >> 2, tgu = rem & 3;
            int sl0 = K0l*16 + 2*tgu;
            uint2 val = make_uint2(pkh(Vsm[(sl0    )*36 + el], Vsm[(sl0 + 1)*36 + el]),
                                   pkh(Vsm[(sl0 + 8)*36 + el], Vsm[(sl0 + 9)*36 + el]));
            int e = ns*32 + el;
            *(uint2*)&vf[(size_t)e*512 + ((s0 >> 4) + K0l)*8 + tgu*2] = val;
        }
    }
}

// ---------------------------------------------------------------------------
// Kernel 2: fp16 tensor-core causal flash attention. Unit-swizzled K/V smem
// (slot = u ^ ((row&3)<<2)) -> conflict-free 2-phase LDS.64 fragment loads.
// 64-key stages, 3-stage ring, 1 barrier/tile, 3 CTAs/SM.
// grid (16, 12, 4); 128 threads.
// ---------------------------------------------------------------------------
#define STW 4096     // words per stage: K 2048 + V 2048 (16KB)

__global__ __launch_bounds__(128, 3)
void attn_kernel(float* __restrict__ out) {
    extern __shared__ uint32_t smu[];

    const int mt = gridDim.x - 1 - blockIdx.x;
    const int h = blockIdx.y, b = blockIdx.z;
    const int tid = threadIdx.x, wid = tid >> 5, lane = tid & 31;
    const int tg = lane >> 2, tig = lane & 3;
    const int m0 = mt * 64;
    const size_t bh = ((size_t)b*HH + h) * SS;
    const float*    gqf = g_Qf + bh*DH;
    const uint32_t* gkf = g_Kf16 + bh*32;
    const uint32_t* gvf = g_Vf16 + ((size_t)b*HH + h) * (DH*SS/2);

    const uint32_t smem_base = (uint32_t)__cvta_generic_to_shared(smu);

    // Q fragments (already scaled by 1/8 in projection): pack to f16x2 pairs.
    uint32_t qa[4][4];
    {
        const int r0 = m0 + wid*16 + tg;
        #pragma unroll
        for (int kk = 0; kk < 4; kk++) {
            float2 lo0 = *(const float2*)&gqf[(size_t)(r0    )*DH + kk*16 + 2*tig];
            float2 lo1 = *(const float2*)&gqf[(size_t)(r0 + 8)*DH + kk*16 + 2*tig];
            float2 hi0 = *(const float2*)&gqf[(size_t)(r0    )*DH + kk*16 + 8 + 2*tig];
            float2 hi1 = *(const float2*)&gqf[(size_t)(r0 + 8)*DH + kk*16 + 8 + 2*tig];
            qa[kk][0] = pkh(lo0.x, lo0.y);
            qa[kk][1] = pkh(lo1.x, lo1.y);
            qa[kk][2] = pkh(hi0.x, hi0.y);
            qa[kk][3] = pkh(hi1.x, hi1.y);
        }
    }

    auto copy_tile = [&](int kt, int stage) {
        const uint32_t sb = smem_base + stage * (STW*4);
        #pragma unroll
        for (int u = 0; u < 4; u++) {
            int idx = tid + u*128;
            int n = idx >> 3, cc = idx & 7;
            int slot = (2*cc) ^ ((n & 3) << 2);
            cpa16(sb + n*128 + slot*8,
                  gkf + ((size_t)(kt*64 + n)*32 + cc*4));
        }
        #pragma unroll
        for (int u = 0; u < 4; u++) {
            int idx = tid + u*128;
            int e = idx >> 3, cc = idx & 7;
            int slot = (2*cc) ^ ((e & 3) << 2);
            cpa16(sb + 2048*4 + e*128 + slot*8,
                  gvf + ((size_t)e*512 + kt*32 + cc*4));
        }
        cpa_commit();
    };

    float o[8][4];
    #pragma unroll
    for (int j = 0; j < 8; j++)
        #pragma unroll
        for (int i = 0; i < 4; i++) o[j][i] = 0.f;
    float mrow[2] = {-1e30f, -1e30f};
    float lrow[2] = {0.f, 0.f};

    copy_tile(0, 0);
    if (mt >= 1) copy_tile(1, 1);

    for (int kt = 0; kt <= mt; kt++) {
        if (kt + 1 <= mt) cpa_wait<1>(); else cpa_wait<0>();
        __syncthreads();
        if (kt + 2 <= mt) copy_tile(kt + 2, (kt + 2) % 3);

        const uint32_t* Kst = smu + (kt % 3)*STW;
        const uint32_t* Vst = Kst + 2048;

        float c[8][4];
        #pragma unroll
        for (int j = 0; j < 8; j++)
            #pragma unroll
            for (int i = 0; i < 4; i++) c[j][i] = 0.f;

        // ---- S = Q K^T : 4 k16-steps x 8 n-blocks ----
        #pragma unroll
        for (int kk = 0; kk < 4; kk++) {
            const int u = kk*4 + tig;
            const int slot = u ^ ((tg & 3) << 2);   // nr&3 == tg&3
            #pragma unroll
            for (int j = 0; j < 8; j++) {
                const int nr = j*8 + tg;
                uint2 kv = *(const uint2*)&Kst[nr*32 + slot*2];
                mma_f16(c[j], qa[kk][0], qa[kk][1], qa[kk][2], qa[kk][3], kv.x, kv.y);
            }
        }

        if (kt == mt) {       // diagonal tile: causal mask
            const int rl0 = wid*16 + tg, rl1 = rl0 + 8;
            #pragma unroll
            for (int j = 0; j < 8; j++) {
                int c0 = j*8 + 2*tig, c1 = c0 + 1;
                if (c0 > rl0) c[j][0] = -1e30f;
                if (c1 > rl0) c[j][1] = -1e30f;
                if (c0 > rl1) c[j][2] = -1e30f;
                if (c1 > rl1) c[j][3] = -1e30f;
            }
        }

        float alpha[2];
        #pragma unroll
        for (int h2 = 0; h2 < 2; h2++) {
            float mx = -1e30f;
            #pragma unroll
            for (int j = 0; j < 8; j++) {
                mx = fmaxf(mx, c[j][h2*2]);
                mx = fmaxf(mx, c[j][h2*2 + 1]);
            }
            mx = fmaxf(mx, __shfl_xor_sync(0xffffffffu, mx, 1));
            mx = fmaxf(mx, __shfl_xor_sync(0xffffffffu, mx, 2));
            float mnew = fmaxf(mrow[h2], mx);
            float sum = 0.f;
            #pragma unroll
            for (int j = 0; j < 8; j++) {
                float p0 = __expf(c[j][h2*2]     - mnew);
                float p1 = __expf(c[j][h2*2 + 1] - mnew);
                c[j][h2*2]     = p0;
                c[j][h2*2 + 1] = p1;
                sum += p0 + p1;
            }
            sum += __shfl_xor_sync(0xffffffffu, sum, 1);
            sum += __shfl_xor_sync(0xffffffffu, sum, 2);
            alpha[h2] = __expf(mrow[h2] - mnew);
            mrow[h2] = mnew;
            lrow[h2] = lrow[h2]*alpha[h2] + sum;
        }

        #pragma unroll
        for (int j = 0; j < 8; j++) {
            o[j][0] *= alpha[0]; o[j][1] *= alpha[0];
            o[j][2] *= alpha[1]; o[j][3] *= alpha[1];
        }

        // ---- O += P V : C-frag pairs ARE the A-frag pairs (no shuffles) ----
        #pragma unroll
        for (int K0 = 0; K0 < 4; K0++) {
            uint32_t a0 = pkh(c[2*K0    ][0], c[2*K0    ][1]);
            uint32_t a1 = pkh(c[2*K0    ][2], c[2*K0    ][3]);
            uint32_t a2 = pkh(c[2*K0 + 1][0], c[2*K0 + 1][1]);
            uint32_t a3 = pkh(c[2*K0 + 1][2], c[2*K0 + 1][3]);
            const int u = K0*4 + tig;
            const int slot = u ^ ((tg & 3) << 2);   // e&3 == tg&3
            #pragma unroll
            for (int jn = 0; jn < 8; jn++) {
                const int e = jn*8 + tg;
                uint2 vv = *(const uint2*)&Vst[e*32 + slot*2];
                mma_f16(o[jn], a0, a1, a2, a3, vv.x, vv.y);
            }
        }
        // stage reuse sealed by the barrier at iteration kt+2
    }

    const float inv0 = 1.f / lrow[0], inv1 = 1.f / lrow[1];
    const int r0 = m0 + wid*16 + tg;
    #pragma unroll
    for (int j = 0; j < 8; j++) {
        int col = h*DH + j*8 + 2*tig;
        *(float2*)&out[((size_t)b*SS + r0    )*(HH*DH) + col] =
            make_float2(o[j][0]*inv0, o[j][1]*inv0);
        *(float2*)&out[((size_t)b*SS + r0 + 8)*(HH*DH) + col] =
            make_float2(o[j][2]*inv1, o[j][3]*inv1);
    }
}

// ---------------------------------------------------------------------------
extern "C" void kernel_launch(void* const* d_in, const int* in_sizes, int n_in,
                              void* d_out, int out_size) {
    const float* x  = (const float*)d_in[0];
    const float* Wq = (const float*)d_in[1];
    const float* Wk = (const float*)d_in[2];
    const float* Wv = (const float*)d_in[3];
    float* out = (float*)d_out;

    prep_x<<<768, 256>>>(x);
    prep_w<<<dim3(24, HH, 3), 256>>>(Wq, Wk, Wv);

    const int proj_smem = 3 * PSTG * (int)sizeof(uint32_t);        // 86,016 B
    cudaFuncSetAttribute(qkv_proj_kernel, cudaFuncAttributeMaxDynamicSharedMemorySize,
                         proj_smem);
    qkv_proj_kernel<<<dim3((BB*SS)/128, HH, 2), 256, proj_smem>>>();

    const int attn_smem = 3 * STW * (int)sizeof(uint32_t);         // 49,152 B
    cudaFuncSetAttribute(attn_kernel, cudaFuncAttributeMaxDynamicSharedMemorySize,
                         attn_smem);
    attn_kernel<<<dim3(SS/64, HH, BB), 128, attn_smem>>>(out);
}